// round 8
// baseline (speedup 1.0000x reference)
#include <cuda_runtime.h>
#include <cuda_fp16.h>
#include <cstdint>
#include <stdint.h>
#include <math.h>

#define DD 128
#define NMAX 50000
#define EMAX 800000
#define SROW 136            // smem row stride in halfs (272B, 16B-multiple)

// ---------------- scratch (static device globals) ----------------
__device__ __align__(16) float  g_recon[(size_t)NMAX * DD];   // recon (fp32, loss input)
__device__ __align__(16) __half g_S[(size_t)NMAX * DD];       // rs_out-scaled gather rows
__device__ __align__(16) __half g_agg16[(size_t)NMAX * DD];   // aggregation output (fp16)
__device__ __align__(16) __half g_h2[(size_t)NMAX * DD];      // encoder layer-2 output
__device__ __align__(16) float  g_token[DD];
__device__ int   g_deg_out[NMAX];
__device__ int   g_deg_in[NMAX];
__device__ float g_rs_out[NMAX];
__device__ float g_rs_in[NMAX];
__device__ int   g_maskflag[NMAX];
__device__ int   g_rowptr[NMAX + 1];
__device__ int   g_fill[NMAX];
__device__ int   g_csrc[EMAX];

// ---------------- setup kernels ----------------
// init counters/flags + token copy + out zero (token: global threads 0..127)
__global__ void k_init(const float* __restrict__ token, float* __restrict__ tok,
                       int* __restrict__ deg_out, int* __restrict__ deg_in,
                       int* __restrict__ fill, int* __restrict__ maskflag,
                       float* __restrict__ out, int n) {
    int i = blockIdx.x * blockDim.x + threadIdx.x;
    if (i < n) { deg_out[i] = 0; deg_in[i] = 0; fill[i] = 0; maskflag[i] = 0; }
    if (i < DD) tok[i] = token[i];
    if (i == 0) out[0] = 0.f;
}

__global__ void k_deg(const int* __restrict__ src, const int* __restrict__ dst,
                      int* __restrict__ dout, int* __restrict__ din, int e) {
    int i = blockIdx.x * blockDim.x + threadIdx.x;
    if (i < e) {
        atomicAdd(&dout[src[i]], 1);
        atomicAdd(&din[dst[i]], 1);
    }
}

// mark mask nodes + rsqrt norms (both depend only on init+deg)
__global__ void k_post(const int* __restrict__ mask_nodes, int* __restrict__ maskflag, int m,
                       const int* __restrict__ dout, const int* __restrict__ din,
                       float* __restrict__ ro, float* __restrict__ ri, int n) {
    int i = blockIdx.x * blockDim.x + threadIdx.x;
    if (i < n) {
        ro[i] = rsqrtf(fmaxf((float)dout[i], 1.f));
        ri[i] = rsqrtf(fmaxf((float)din[i], 1.f));
    }
    if (i < m) maskflag[mask_nodes[i]] = 1;
}

__global__ void __launch_bounds__(1024)
k_scan(const int* __restrict__ deg, int* __restrict__ rowptr, int n) {
    __shared__ int part[1024];
    int t = threadIdx.x;
    int chunk = (n + 1023) / 1024;
    int lo = t * chunk;
    int hi = lo + chunk; if (hi > n) hi = n; if (lo > n) lo = n;
    int s = 0;
    for (int i = lo; i < hi; i++) s += deg[i];
    part[t] = s;
    __syncthreads();
    for (int o = 1; o < 1024; o <<= 1) {
        int v = (t >= o) ? part[t - o] : 0;
        __syncthreads();
        part[t] += v;
        __syncthreads();
    }
    int base = (t == 0) ? 0 : part[t - 1];
    for (int i = lo; i < hi; i++) {
        rowptr[i] = base;
        base += deg[i];
    }
    if (t == 1023) rowptr[n] = part[1023];
}

__global__ void k_fill(const int* __restrict__ src, const int* __restrict__ dst,
                       const int* __restrict__ rowptr, int* __restrict__ fill,
                       int* __restrict__ csrc, int e) {
    int i = blockIdx.x * blockDim.x + threadIdx.x;
    if (i < e) {
        int d = dst[i];
        int p = rowptr[d] + atomicAdd(&fill[d], 1);
        csrc[p] = src[i];
    }
}

// ---------------- prep: S[v] = (mask? token : x[v]) * rs_out[v] fp16 ----------------
__global__ void __launch_bounds__(256)
k_prep1(const float* __restrict__ x, const float* __restrict__ token,
        const int* __restrict__ maskflag, const float* __restrict__ rs_out,
        __half* __restrict__ S, int n) {
    int w = (blockIdx.x * blockDim.x + threadIdx.x) >> 5;
    int lane = threadIdx.x & 31;
    if (w >= n) return;
    float r = rs_out[w];
    const float* srcp = maskflag[w] ? (token + lane * 4) : (x + (size_t)w * DD + lane * 4);
    __half2 p0 = __floats2half2_rn(srcp[0] * r, srcp[1] * r);
    __half2 p1 = __floats2half2_rn(srcp[2] * r, srcp[3] * r);
    uint2 u;
    *(__half2*)&u.x = p0;
    *(__half2*)&u.y = p1;
    ((uint2*)S)[(size_t)w * 32 + lane] = u;
}

// ---------------- CSR aggregation, 2 edges/iteration ----------------
// warp per node. Lanes 0-15 gather edge e (16B chunks of the 256B row),
// lanes 16-31 gather edge e+1. Combine half-warps with shfl_xor(16); lanes 0-15 write.
__global__ void __launch_bounds__(256)
k_agg(const __half* __restrict__ S,
      const int* __restrict__ rowptr, const int* __restrict__ csrc,
      __half* __restrict__ agg, int n) {
    int w = (blockIdx.x * blockDim.x + threadIdx.x) >> 5;
    int lane = threadIdx.x & 31;
    if (w >= n) return;
    int beg = rowptr[w];
    int end = rowptr[w + 1];
    int half = lane >> 4;
    int sub  = lane & 15;

    float a0 = 0.f, a1 = 0.f, a2 = 0.f, a3 = 0.f, a4 = 0.f, a5 = 0.f, a6 = 0.f, a7 = 0.f;
    for (int e = beg; e < end; e += 2) {
        int idx = e + half;
        if (idx < end) {
            int s = csrc[idx];
            uint4 u = ((const uint4*)S)[(size_t)s * 16 + sub];
            float2 f0 = __half22float2(*(__half2*)&u.x);
            float2 f1 = __half22float2(*(__half2*)&u.y);
            float2 f2 = __half22float2(*(__half2*)&u.z);
            float2 f3 = __half22float2(*(__half2*)&u.w);
            a0 += f0.x; a1 += f0.y; a2 += f1.x; a3 += f1.y;
            a4 += f2.x; a5 += f2.y; a6 += f3.x; a7 += f3.y;
        }
    }
    a0 += __shfl_xor_sync(0xffffffffu, a0, 16);
    a1 += __shfl_xor_sync(0xffffffffu, a1, 16);
    a2 += __shfl_xor_sync(0xffffffffu, a2, 16);
    a3 += __shfl_xor_sync(0xffffffffu, a3, 16);
    a4 += __shfl_xor_sync(0xffffffffu, a4, 16);
    a5 += __shfl_xor_sync(0xffffffffu, a5, 16);
    a6 += __shfl_xor_sync(0xffffffffu, a6, 16);
    a7 += __shfl_xor_sync(0xffffffffu, a7, 16);
    if (lane < 16) {
        uint4 o;
        *(__half2*)&o.x = __floats2half2_rn(a0, a1);
        *(__half2*)&o.y = __floats2half2_rn(a2, a3);
        *(__half2*)&o.z = __floats2half2_rn(a4, a5);
        *(__half2*)&o.w = __floats2half2_rn(a6, a7);
        ((uint4*)agg)[(size_t)w * 16 + sub] = o;
    }
}

// ---------------- tensor-core GEMM: out = in(fp16) @ W^T + epilogue ----------------
// mode 0: (acc+b)*rs_in -> LN -> PReLU -> fp16 (optionally *rs_out)   [encoder layers]
// mode 1: (acc+b)*rs_in -> fp32                                        [decoder conv]
// mode 2: acc, re-mask, *rs_out -> fp16                                [enc->dec]
__global__ void __launch_bounds__(256, 2)
k_gemm(const __half* __restrict__ in, __half* __restrict__ outh, float* __restrict__ outf,
       const float* __restrict__ W, const float* __restrict__ bias,
       const float* __restrict__ rs_in, const float* __restrict__ rs_out,
       const float* __restrict__ gamma, const float* __restrict__ beta,
       const float* __restrict__ alpha,
       const int* __restrict__ maskflag,
       int n, int mode, int scale_rso) {
    extern __shared__ char smraw[];
    __half* sA = (__half*)smraw;                    // [128][SROW]
    __half* sW = sA + 128 * SROW;                   // [128][SROW]
    float* sBias  = (float*)(sW + 128 * SROW);      // [128]
    float* sGamma = sBias + 128;                    // [128]
    float* sBeta  = sGamma + 128;                   // [128]

    const int tid  = threadIdx.x;
    const int row0 = blockIdx.x * 128;

    // ---- stage A tile (uint4 = 8 halfs) ----
    #pragma unroll
    for (int it = 0; it < 8; it++) {
        int idx = it * 256 + tid;                   // 0..2047
        int r = idx >> 4, c8 = idx & 15;
        uint4 v = make_uint4(0u, 0u, 0u, 0u);
        int gr = row0 + r;
        if (gr < n) v = ((const uint4*)in)[(size_t)gr * 16 + c8];
        *(uint4*)&sA[r * SROW + c8 * 8] = v;
    }
    // ---- stage W tile (external fp32 -> fp16, scalar-pair loads) ----
    #pragma unroll
    for (int it = 0; it < 32; it++) {
        int idx = it * 256 + tid;                   // pair index 0..8191
        int base2 = idx * 2;
        int cc = base2 >> 7, kk = base2 & 127;
        float w0 = W[base2], w1 = W[base2 + 1];
        *(__half2*)&sW[cc * SROW + kk] = __floats2half2_rn(w0, w1);
    }
    if (tid < 128) {
        sBias[tid]  = (mode != 2) ? bias[tid] : 0.f;
        sGamma[tid] = (mode == 0) ? gamma[tid] : 0.f;
        sBeta[tid]  = (mode == 0) ? beta[tid] : 0.f;
    }
    __syncthreads();

    const int warp = tid >> 5;
    const int lane = tid & 31;

    float c[16][4];
    #pragma unroll
    for (int i = 0; i < 16; i++) {
        c[i][0] = 0.f; c[i][1] = 0.f; c[i][2] = 0.f; c[i][3] = 0.f;
    }

    uint32_t sAu = (uint32_t)__cvta_generic_to_shared(sA);
    uint32_t sWu = (uint32_t)__cvta_generic_to_shared(sW);
    uint32_t aBase = sAu + (uint32_t)((warp * 16 + (lane & 15)) * (SROW * 2) + (lane >> 4) * 16);
    uint32_t bRow  = (uint32_t)((lane >> 4) * 8 + (lane & 7));
    uint32_t bKoff = (uint32_t)(((lane >> 3) & 1) * 16);

    #pragma unroll
    for (int kb = 0; kb < 8; kb++) {
        uint32_t a0, a1, a2, a3;
        asm volatile("ldmatrix.sync.aligned.m8n8.x4.shared.b16 {%0,%1,%2,%3}, [%4];"
                     : "=r"(a0), "=r"(a1), "=r"(a2), "=r"(a3)
                     : "r"(aBase + kb * 32));
        #pragma unroll
        for (int ng = 0; ng < 8; ng++) {
            uint32_t b0, b1, b2, b3;
            uint32_t baddr = sWu + (uint32_t)((ng * 16 + bRow) * (SROW * 2) + kb * 32 + bKoff);
            asm volatile("ldmatrix.sync.aligned.m8n8.x4.shared.b16 {%0,%1,%2,%3}, [%4];"
                         : "=r"(b0), "=r"(b1), "=r"(b2), "=r"(b3)
                         : "r"(baddr));
            int t0 = ng * 2, t1 = ng * 2 + 1;
            asm volatile("mma.sync.aligned.m16n8k16.row.col.f32.f16.f16.f32 "
                         "{%0,%1,%2,%3}, {%4,%5,%6,%7}, {%8,%9}, {%0,%1,%2,%3};"
                         : "+f"(c[t0][0]), "+f"(c[t0][1]), "+f"(c[t0][2]), "+f"(c[t0][3])
                         : "r"(a0), "r"(a1), "r"(a2), "r"(a3), "r"(b0), "r"(b1));
            asm volatile("mma.sync.aligned.m16n8k16.row.col.f32.f16.f16.f32 "
                         "{%0,%1,%2,%3}, {%4,%5,%6,%7}, {%8,%9}, {%0,%1,%2,%3};"
                         : "+f"(c[t1][0]), "+f"(c[t1][1]), "+f"(c[t1][2]), "+f"(c[t1][3])
                         : "r"(a0), "r"(a1), "r"(a2), "r"(a3), "r"(b2), "r"(b3));
        }
    }

    // ---- epilogue ----
    int r0 = row0 + warp * 16 + (lane >> 2);
    int r1 = r0 + 8;
    int q  = lane & 3;

    if (mode == 2) {
        float rso0 = (r0 < n) ? ((maskflag[r0]) ? 0.f : (scale_rso ? rs_out[r0] : 1.f)) : 0.f;
        float rso1 = (r1 < n) ? ((maskflag[r1]) ? 0.f : (scale_rso ? rs_out[r1] : 1.f)) : 0.f;
        #pragma unroll
        for (int ct = 0; ct < 16; ct++) {
            int ci = ct * 4 + q;
            if (r0 < n) ((__half2*)outh)[(size_t)r0 * 64 + ci] = __floats2half2_rn(c[ct][0] * rso0, c[ct][1] * rso0);
            if (r1 < n) ((__half2*)outh)[(size_t)r1 * 64 + ci] = __floats2half2_rn(c[ct][2] * rso1, c[ct][3] * rso1);
        }
        return;
    }

    float rsi0 = (r0 < n) ? rs_in[r0] : 1.f;
    float rsi1 = (r1 < n) ? rs_in[r1] : 1.f;
    #pragma unroll
    for (int ct = 0; ct < 16; ct++) {
        int colb = ct * 8 + q * 2;
        float bb0 = sBias[colb], bb1 = sBias[colb + 1];
        c[ct][0] = (c[ct][0] + bb0) * rsi0;
        c[ct][1] = (c[ct][1] + bb1) * rsi0;
        c[ct][2] = (c[ct][2] + bb0) * rsi1;
        c[ct][3] = (c[ct][3] + bb1) * rsi1;
    }

    if (mode == 1) {
        #pragma unroll
        for (int ct = 0; ct < 16; ct++) {
            int ci = ct * 4 + q;
            if (r0 < n) ((float2*)outf)[(size_t)r0 * 64 + ci] = make_float2(c[ct][0], c[ct][1]);
            if (r1 < n) ((float2*)outf)[(size_t)r1 * 64 + ci] = make_float2(c[ct][2], c[ct][3]);
        }
        return;
    }

    // mode 0: LayerNorm (quad reduction) + PReLU
    float s0 = 0.f, ss0 = 0.f, s1 = 0.f, ss1 = 0.f;
    #pragma unroll
    for (int ct = 0; ct < 16; ct++) {
        s0  += c[ct][0] + c[ct][1];
        ss0 += c[ct][0] * c[ct][0] + c[ct][1] * c[ct][1];
        s1  += c[ct][2] + c[ct][3];
        ss1 += c[ct][2] * c[ct][2] + c[ct][3] * c[ct][3];
    }
    #pragma unroll
    for (int o = 1; o <= 2; o <<= 1) {
        s0  += __shfl_xor_sync(0xffffffffu, s0,  o);
        ss0 += __shfl_xor_sync(0xffffffffu, ss0, o);
        s1  += __shfl_xor_sync(0xffffffffu, s1,  o);
        ss1 += __shfl_xor_sync(0xffffffffu, ss1, o);
    }
    float mu0 = s0 * (1.f / 128.f);
    float mu1 = s1 * (1.f / 128.f);
    float inv0 = rsqrtf(ss0 * (1.f / 128.f) - mu0 * mu0 + 1e-5f);
    float inv1 = rsqrtf(ss1 * (1.f / 128.f) - mu1 * mu1 + 1e-5f);
    float aP = alpha[0];
    float rso0 = 1.f, rso1 = 1.f;
    if (scale_rso) {
        rso0 = (r0 < n) ? rs_out[r0] : 1.f;
        rso1 = (r1 < n) ? rs_out[r1] : 1.f;
    }
    #pragma unroll
    for (int ct = 0; ct < 16; ct++) {
        int colb = ct * 8 + q * 2;
        float g0 = sGamma[colb], g1 = sGamma[colb + 1];
        float e0 = sBeta[colb],  e1 = sBeta[colb + 1];
        float y0 = (c[ct][0] - mu0) * inv0 * g0 + e0; y0 = (y0 >= 0.f) ? y0 : aP * y0;
        float y1 = (c[ct][1] - mu0) * inv0 * g1 + e1; y1 = (y1 >= 0.f) ? y1 : aP * y1;
        float y2 = (c[ct][2] - mu1) * inv1 * g0 + e0; y2 = (y2 >= 0.f) ? y2 : aP * y2;
        float y3 = (c[ct][3] - mu1) * inv1 * g1 + e1; y3 = (y3 >= 0.f) ? y3 : aP * y3;
        int ci = ct * 4 + q;
        if (r0 < n) ((__half2*)outh)[(size_t)r0 * 64 + ci] = __floats2half2_rn(y0 * rso0, y1 * rso0);
        if (r1 < n) ((__half2*)outh)[(size_t)r1 * 64 + ci] = __floats2half2_rn(y2 * rso1, y3 * rso1);
    }
}

// ---------------- SCE loss over masked rows ----------------
__global__ void __launch_bounds__(256)
k_loss(const float* __restrict__ recon, const float* __restrict__ x,
       const int* __restrict__ mask_nodes, int m, float* __restrict__ out) {
    __shared__ float part[8];
    int gw   = (blockIdx.x * blockDim.x + threadIdx.x) >> 5;
    int lane = threadIdx.x & 31;
    int wl   = threadIdx.x >> 5;
    float term = 0.f;
    if (gw < m) {
        int node = mask_nodes[gw];
        float4 r = ((const float4*)recon)[(size_t)node * 32 + lane];
        const float* xp = x + (size_t)node * DD + lane * 4;
        float x0 = xp[0], x1 = xp[1], x2 = xp[2], x3 = xp[3];
        float dot = r.x * x0 + r.y * x1 + r.z * x2 + r.w * x3;
        float nr  = r.x * r.x + r.y * r.y + r.z * r.z + r.w * r.w;
        float nx  = x0 * x0 + x1 * x1 + x2 * x2 + x3 * x3;
        #pragma unroll
        for (int o = 16; o; o >>= 1) {
            dot += __shfl_xor_sync(0xffffffffu, dot, o);
            nr  += __shfl_xor_sync(0xffffffffu, nr,  o);
            nx  += __shfl_xor_sync(0xffffffffu, nx,  o);
        }
        if (lane == 0) {
            float cc = dot / (fmaxf(sqrtf(nr), 1e-12f) * fmaxf(sqrtf(nx), 1e-12f));
            float t = 1.f - cc;
            term = t * t;
        }
    }
    if (lane == 0) part[wl] = term;
    __syncthreads();
    if (threadIdx.x == 0) {
        float s = 0.f;
        #pragma unroll
        for (int i = 0; i < 8; i++) s += part[i];
        atomicAdd(out, s / (float)m);
    }
}

// ---------------- launch ----------------
extern "C" void kernel_launch(void* const* d_in, const int* in_sizes, int n_in,
                              void* d_out, int out_size) {
    const float* x     = (const float*)d_in[0];
    const float* token = (const float*)d_in[1];
    const float* W1    = (const float*)d_in[2];
    const float* b1    = (const float*)d_in[3];
    const float* g1    = (const float*)d_in[4];
    const float* be1   = (const float*)d_in[5];
    const float* a1    = (const float*)d_in[6];
    const float* W2    = (const float*)d_in[7];
    const float* b2    = (const float*)d_in[8];
    const float* g2    = (const float*)d_in[9];
    const float* be2   = (const float*)d_in[10];
    const float* a2    = (const float*)d_in[11];
    const float* We2d  = (const float*)d_in[12];
    const float* Wd    = (const float*)d_in[13];
    const float* bd    = (const float*)d_in[14];
    const int*   src   = (const int*)d_in[15];
    const int*   dst   = (const int*)d_in[16];
    const int*   mask  = (const int*)d_in[17];

    const int n = in_sizes[0] / DD;
    const int E = in_sizes[15];
    const int M = in_sizes[17];
    float* out = (float*)d_out;

    float *recon, *tokA, *rs_out, *rs_in;
    __half *S, *agg16, *h2;
    int *deg_out, *deg_in, *maskflag, *rowptr, *fill, *csrc;
    cudaGetSymbolAddress((void**)&recon, g_recon);
    cudaGetSymbolAddress((void**)&S,     g_S);
    cudaGetSymbolAddress((void**)&agg16, g_agg16);
    cudaGetSymbolAddress((void**)&h2,    g_h2);
    cudaGetSymbolAddress((void**)&tokA,  g_token);
    cudaGetSymbolAddress((void**)&deg_out, g_deg_out);
    cudaGetSymbolAddress((void**)&deg_in,  g_deg_in);
    cudaGetSymbolAddress((void**)&rs_out, g_rs_out);
    cudaGetSymbolAddress((void**)&rs_in,  g_rs_in);
    cudaGetSymbolAddress((void**)&maskflag, g_maskflag);
    cudaGetSymbolAddress((void**)&rowptr, g_rowptr);
    cudaGetSymbolAddress((void**)&fill,   g_fill);
    cudaGetSymbolAddress((void**)&csrc,   g_csrc);

    const size_t smem = (size_t)(2 * 128 * SROW) * sizeof(__half) + 3 * 128 * sizeof(float);
    cudaFuncSetAttribute(k_gemm, cudaFuncAttributeMaxDynamicSharedMemorySize, (int)smem);

    const int T = 256;
    const int gN = (n + T - 1) / T;
    const int gE = (E + T - 1) / T;
    const int gW = ((n * 32) + T - 1) / T;
    const int gG = (n + 127) / 128;
    const int gL = ((M * 32) + T - 1) / T;

    // setup
    k_init <<<gN, T>>>(token, tokA, deg_out, deg_in, fill, maskflag, out, n);
    k_deg  <<<gE, T>>>(src, dst, deg_out, deg_in, E);
    k_post <<<gN, T>>>(mask, maskflag, M, deg_out, deg_in, rs_out, rs_in, n);
    k_scan <<<1, 1024>>>(deg_in, rowptr, n);
    k_fill <<<gE, T>>>(src, dst, rowptr, fill, csrc, E);

    // conv1: prep -> agg -> GEMM(LN+PReLU, *rs_out) -> S
    k_prep1<<<gW, T>>>(x, tokA, maskflag, rs_out, S, n);
    k_agg  <<<gW, T>>>(S, rowptr, csrc, agg16, n);
    k_gemm <<<gG, 256, smem>>>(agg16, S, nullptr, W1, b1, rs_in, rs_out, g1, be1, a1, maskflag, n, 0, 1);

    // conv2: agg -> GEMM(LN+PReLU) -> h2
    k_agg  <<<gW, T>>>(S, rowptr, csrc, agg16, n);
    k_gemm <<<gG, 256, smem>>>(agg16, h2, nullptr, W2, b2, rs_in, rs_out, g2, be2, a2, maskflag, n, 0, 0);

    // enc->dec + re-mask, *rs_out -> S
    k_gemm <<<gG, 256, smem>>>(h2, S, nullptr, We2d, bd, rs_in, rs_out, g2, be2, a2, maskflag, n, 2, 1);

    // decoder conv: agg -> GEMM(bias+rs_in) -> recon (fp32)
    k_agg  <<<gW, T>>>(S, rowptr, csrc, agg16, n);
    k_gemm <<<gG, 256, smem>>>(agg16, nullptr, recon, Wd, bd, rs_in, rs_out, g2, be2, a2, maskflag, n, 1, 0);

    // loss
    k_loss <<<gL, T>>>(recon, x, mask, M, out);
}

// round 9
// speedup vs baseline: 1.3182x; 1.3182x over previous
#include <cuda_runtime.h>
#include <cuda_fp16.h>
#include <cstdint>
#include <stdint.h>
#include <math.h>

#define DD 128
#define NMAX 50000
#define EMAX 800000
#define SROW 136            // smem row stride in halfs (272B, 16B-multiple)

// ---------------- scratch (static device globals) ----------------
__device__ __align__(16) float  g_recon[(size_t)NMAX * DD];   // recon (fp32, loss input)
__device__ __align__(16) __half g_S[(size_t)NMAX * DD];       // rs_out-scaled gather rows
__device__ __align__(16) __half g_agg16[(size_t)NMAX * DD];   // aggregation output (fp16)
__device__ __align__(16) __half g_h2[(size_t)NMAX * DD];      // encoder layer-2 output
__device__ __align__(16) float  g_token[DD];
__device__ int   g_deg_out[NMAX];
__device__ int   g_deg_in[NMAX];
__device__ float g_rs_out[NMAX];
__device__ float g_rs_in[NMAX];
__device__ int   g_maskflag[NMAX];
__device__ int   g_rowptr[NMAX + 1];
__device__ int   g_fill[NMAX];
__device__ int   g_bsum[128];
__device__ int   g_csrc[EMAX];

// ---------------- setup kernels ----------------
__global__ void k_init(const float* __restrict__ token, float* __restrict__ tok,
                       int* __restrict__ deg_out, int* __restrict__ deg_in,
                       int* __restrict__ fill, int* __restrict__ maskflag,
                       float* __restrict__ out, int n) {
    int i = blockIdx.x * blockDim.x + threadIdx.x;
    if (i < n) { deg_out[i] = 0; deg_in[i] = 0; fill[i] = 0; maskflag[i] = 0; }
    if (i < DD) tok[i] = token[i];
    if (i == 0) out[0] = 0.f;
}

__global__ void k_deg(const int* __restrict__ src, const int* __restrict__ dst,
                      int* __restrict__ dout, int* __restrict__ din, int e) {
    int i = blockIdx.x * blockDim.x + threadIdx.x;
    if (i < e) {
        atomicAdd(&dout[src[i]], 1);
        atomicAdd(&din[dst[i]], 1);
    }
}

__global__ void k_post(const int* __restrict__ mask_nodes, int* __restrict__ maskflag, int m,
                       const int* __restrict__ dout, const int* __restrict__ din,
                       float* __restrict__ ro, float* __restrict__ ri, int n) {
    int i = blockIdx.x * blockDim.x + threadIdx.x;
    if (i < n) {
        ro[i] = rsqrtf(fmaxf((float)dout[i], 1.f));
        ri[i] = rsqrtf(fmaxf((float)din[i], 1.f));
    }
    if (i < m) maskflag[mask_nodes[i]] = 1;
}

// ---------------- parallel exclusive scan: 3 passes over 1024-elem tiles ----------------
// pass 1: per-block exclusive scan (shuffle-based), block totals to bsum
__global__ void __launch_bounds__(1024)
k_scan1(const int* __restrict__ deg, int* __restrict__ rowptr,
        int* __restrict__ bsum, int n) {
    __shared__ int warpsum[32];
    int t = threadIdx.x;
    int gi = blockIdx.x * 1024 + t;
    int v = (gi < n) ? deg[gi] : 0;
    int lane = t & 31, wid = t >> 5;
    int inc = v;
    #pragma unroll
    for (int o = 1; o < 32; o <<= 1) {
        int u = __shfl_up_sync(0xffffffffu, inc, o);
        if (lane >= o) inc += u;
    }
    if (lane == 31) warpsum[wid] = inc;
    __syncthreads();
    if (wid == 0) {
        int w = warpsum[lane];
        #pragma unroll
        for (int o = 1; o < 32; o <<= 1) {
            int u = __shfl_up_sync(0xffffffffu, w, o);
            if (lane >= o) w += u;
        }
        warpsum[lane] = w;
    }
    __syncthreads();
    int woff = (wid > 0) ? warpsum[wid - 1] : 0;
    if (gi <= n) rowptr[gi] = woff + inc - v;   // exclusive
    if (t == 1023) bsum[blockIdx.x] = warpsum[31];
}

// pass 2: scan block sums (single small block)
__global__ void k_scan2(int* __restrict__ bsum, int nb) {
    __shared__ int sm[128];
    int t = threadIdx.x;
    sm[t] = (t < nb) ? bsum[t] : 0;
    __syncthreads();
    #pragma unroll
    for (int o = 1; o < 128; o <<= 1) {
        int v = (t >= o) ? sm[t - o] : 0;
        __syncthreads();
        sm[t] += v;
        __syncthreads();
    }
    if (t < nb) bsum[t] = (t > 0) ? sm[t - 1] : 0;   // exclusive offsets
}

// pass 3: add block offsets
__global__ void __launch_bounds__(1024)
k_scan3(int* __restrict__ rowptr, const int* __restrict__ bsum, int n) {
    int gi = blockIdx.x * 1024 + threadIdx.x;
    if (gi <= n) rowptr[gi] += bsum[blockIdx.x];
}

__global__ void k_fill(const int* __restrict__ src, const int* __restrict__ dst,
                       const int* __restrict__ rowptr, int* __restrict__ fill,
                       int* __restrict__ csrc, int e) {
    int i = blockIdx.x * blockDim.x + threadIdx.x;
    if (i < e) {
        int d = dst[i];
        int p = rowptr[d] + atomicAdd(&fill[d], 1);
        csrc[p] = src[i];
    }
}

// ---------------- prep: S[v] = (mask? token : x[v]) * rs_out[v] fp16 ----------------
__global__ void __launch_bounds__(256)
k_prep1(const float* __restrict__ x, const float* __restrict__ token,
        const int* __restrict__ maskflag, const float* __restrict__ rs_out,
        __half* __restrict__ S, int n) {
    int w = (blockIdx.x * blockDim.x + threadIdx.x) >> 5;
    int lane = threadIdx.x & 31;
    if (w >= n) return;
    float r = rs_out[w];
    const float* srcp = maskflag[w] ? (token + lane * 4) : (x + (size_t)w * DD + lane * 4);
    __half2 p0 = __floats2half2_rn(srcp[0] * r, srcp[1] * r);
    __half2 p1 = __floats2half2_rn(srcp[2] * r, srcp[3] * r);
    uint2 u;
    *(__half2*)&u.x = p0;
    *(__half2*)&u.y = p1;
    ((uint2*)S)[(size_t)w * 32 + lane] = u;
}

// ---------------- CSR aggregation (R7 shape: 1 edge/iter, uint2 per lane) ----------------
__global__ void __launch_bounds__(256)
k_agg(const __half* __restrict__ S,
      const int* __restrict__ rowptr, const int* __restrict__ csrc,
      __half* __restrict__ agg, int n) {
    int w = (blockIdx.x * blockDim.x + threadIdx.x) >> 5;
    int lane = threadIdx.x & 31;
    if (w >= n) return;
    int beg = rowptr[w];
    int end = rowptr[w + 1];
    float4 acc = make_float4(0.f, 0.f, 0.f, 0.f);
    for (int e = beg; e < end; e++) {
        int s = csrc[e];
        uint2 u = ((const uint2*)S)[(size_t)s * 32 + lane];
        float2 f0 = __half22float2(*(__half2*)&u.x);
        float2 f1 = __half22float2(*(__half2*)&u.y);
        acc.x += f0.x; acc.y += f0.y; acc.z += f1.x; acc.w += f1.y;
    }
    uint2 o;
    *(__half2*)&o.x = __floats2half2_rn(acc.x, acc.y);
    *(__half2*)&o.y = __floats2half2_rn(acc.z, acc.w);
    ((uint2*)agg)[(size_t)w * 32 + lane] = o;
}

// ---------------- tensor-core GEMM: out = in(fp16) @ W^T + epilogue ----------------
__global__ void __launch_bounds__(256, 2)
k_gemm(const __half* __restrict__ in, __half* __restrict__ outh, float* __restrict__ outf,
       const float* __restrict__ W, const float* __restrict__ bias,
       const float* __restrict__ rs_in, const float* __restrict__ rs_out,
       const float* __restrict__ gamma, const float* __restrict__ beta,
       const float* __restrict__ alpha,
       const int* __restrict__ maskflag,
       int n, int mode, int scale_rso) {
    extern __shared__ char smraw[];
    __half* sA = (__half*)smraw;                    // [128][SROW]
    __half* sW = sA + 128 * SROW;                   // [128][SROW]
    float* sBias  = (float*)(sW + 128 * SROW);      // [128]
    float* sGamma = sBias + 128;                    // [128]
    float* sBeta  = sGamma + 128;                   // [128]

    const int tid  = threadIdx.x;
    const int row0 = blockIdx.x * 128;

    #pragma unroll
    for (int it = 0; it < 8; it++) {
        int idx = it * 256 + tid;                   // 0..2047
        int r = idx >> 4, c8 = idx & 15;
        uint4 v = make_uint4(0u, 0u, 0u, 0u);
        int gr = row0 + r;
        if (gr < n) v = ((const uint4*)in)[(size_t)gr * 16 + c8];
        *(uint4*)&sA[r * SROW + c8 * 8] = v;
    }
    #pragma unroll
    for (int it = 0; it < 32; it++) {
        int idx = it * 256 + tid;
        int base2 = idx * 2;
        int cc = base2 >> 7, kk = base2 & 127;
        float w0 = W[base2], w1 = W[base2 + 1];
        *(__half2*)&sW[cc * SROW + kk] = __floats2half2_rn(w0, w1);
    }
    if (tid < 128) {
        sBias[tid]  = (mode != 2) ? bias[tid] : 0.f;
        sGamma[tid] = (mode == 0) ? gamma[tid] : 0.f;
        sBeta[tid]  = (mode == 0) ? beta[tid] : 0.f;
    }
    __syncthreads();

    const int warp = tid >> 5;
    const int lane = tid & 31;

    float c[16][4];
    #pragma unroll
    for (int i = 0; i < 16; i++) {
        c[i][0] = 0.f; c[i][1] = 0.f; c[i][2] = 0.f; c[i][3] = 0.f;
    }

    uint32_t sAu = (uint32_t)__cvta_generic_to_shared(sA);
    uint32_t sWu = (uint32_t)__cvta_generic_to_shared(sW);
    uint32_t aBase = sAu + (uint32_t)((warp * 16 + (lane & 15)) * (SROW * 2) + (lane >> 4) * 16);
    uint32_t bRow  = (uint32_t)((lane >> 4) * 8 + (lane & 7));
    uint32_t bKoff = (uint32_t)(((lane >> 3) & 1) * 16);

    #pragma unroll
    for (int kb = 0; kb < 8; kb++) {
        uint32_t a0, a1, a2, a3;
        asm volatile("ldmatrix.sync.aligned.m8n8.x4.shared.b16 {%0,%1,%2,%3}, [%4];"
                     : "=r"(a0), "=r"(a1), "=r"(a2), "=r"(a3)
                     : "r"(aBase + kb * 32));
        #pragma unroll
        for (int ng = 0; ng < 8; ng++) {
            uint32_t b0, b1, b2, b3;
            uint32_t baddr = sWu + (uint32_t)((ng * 16 + bRow) * (SROW * 2) + kb * 32 + bKoff);
            asm volatile("ldmatrix.sync.aligned.m8n8.x4.shared.b16 {%0,%1,%2,%3}, [%4];"
                         : "=r"(b0), "=r"(b1), "=r"(b2), "=r"(b3)
                         : "r"(baddr));
            int t0 = ng * 2, t1 = ng * 2 + 1;
            asm volatile("mma.sync.aligned.m16n8k16.row.col.f32.f16.f16.f32 "
                         "{%0,%1,%2,%3}, {%4,%5,%6,%7}, {%8,%9}, {%0,%1,%2,%3};"
                         : "+f"(c[t0][0]), "+f"(c[t0][1]), "+f"(c[t0][2]), "+f"(c[t0][3])
                         : "r"(a0), "r"(a1), "r"(a2), "r"(a3), "r"(b0), "r"(b1));
            asm volatile("mma.sync.aligned.m16n8k16.row.col.f32.f16.f16.f32 "
                         "{%0,%1,%2,%3}, {%4,%5,%6,%7}, {%8,%9}, {%0,%1,%2,%3};"
                         : "+f"(c[t1][0]), "+f"(c[t1][1]), "+f"(c[t1][2]), "+f"(c[t1][3])
                         : "r"(a0), "r"(a1), "r"(a2), "r"(a3), "r"(b2), "r"(b3));
        }
    }

    int r0 = row0 + warp * 16 + (lane >> 2);
    int r1 = r0 + 8;
    int q  = lane & 3;

    if (mode == 2) {
        float rso0 = (r0 < n) ? ((maskflag[r0]) ? 0.f : (scale_rso ? rs_out[r0] : 1.f)) : 0.f;
        float rso1 = (r1 < n) ? ((maskflag[r1]) ? 0.f : (scale_rso ? rs_out[r1] : 1.f)) : 0.f;
        #pragma unroll
        for (int ct = 0; ct < 16; ct++) {
            int ci = ct * 4 + q;
            if (r0 < n) ((__half2*)outh)[(size_t)r0 * 64 + ci] = __floats2half2_rn(c[ct][0] * rso0, c[ct][1] * rso0);
            if (r1 < n) ((__half2*)outh)[(size_t)r1 * 64 + ci] = __floats2half2_rn(c[ct][2] * rso1, c[ct][3] * rso1);
        }
        return;
    }

    float rsi0 = (r0 < n) ? rs_in[r0] : 1.f;
    float rsi1 = (r1 < n) ? rs_in[r1] : 1.f;
    #pragma unroll
    for (int ct = 0; ct < 16; ct++) {
        int colb = ct * 8 + q * 2;
        float bb0 = sBias[colb], bb1 = sBias[colb + 1];
        c[ct][0] = (c[ct][0] + bb0) * rsi0;
        c[ct][1] = (c[ct][1] + bb1) * rsi0;
        c[ct][2] = (c[ct][2] + bb0) * rsi1;
        c[ct][3] = (c[ct][3] + bb1) * rsi1;
    }

    if (mode == 1) {
        #pragma unroll
        for (int ct = 0; ct < 16; ct++) {
            int ci = ct * 4 + q;
            if (r0 < n) ((float2*)outf)[(size_t)r0 * 64 + ci] = make_float2(c[ct][0], c[ct][1]);
            if (r1 < n) ((float2*)outf)[(size_t)r1 * 64 + ci] = make_float2(c[ct][2], c[ct][3]);
        }
        return;
    }

    float s0 = 0.f, ss0 = 0.f, s1 = 0.f, ss1 = 0.f;
    #pragma unroll
    for (int ct = 0; ct < 16; ct++) {
        s0  += c[ct][0] + c[ct][1];
        ss0 += c[ct][0] * c[ct][0] + c[ct][1] * c[ct][1];
        s1  += c[ct][2] + c[ct][3];
        ss1 += c[ct][2] * c[ct][2] + c[ct][3] * c[ct][3];
    }
    #pragma unroll
    for (int o = 1; o <= 2; o <<= 1) {
        s0  += __shfl_xor_sync(0xffffffffu, s0,  o);
        ss0 += __shfl_xor_sync(0xffffffffu, ss0, o);
        s1  += __shfl_xor_sync(0xffffffffu, s1,  o);
        ss1 += __shfl_xor_sync(0xffffffffu, ss1, o);
    }
    float mu0 = s0 * (1.f / 128.f);
    float mu1 = s1 * (1.f / 128.f);
    float inv0 = rsqrtf(ss0 * (1.f / 128.f) - mu0 * mu0 + 1e-5f);
    float inv1 = rsqrtf(ss1 * (1.f / 128.f) - mu1 * mu1 + 1e-5f);
    float aP = alpha[0];
    float rso0 = 1.f, rso1 = 1.f;
    if (scale_rso) {
        rso0 = (r0 < n) ? rs_out[r0] : 1.f;
        rso1 = (r1 < n) ? rs_out[r1] : 1.f;
    }
    #pragma unroll
    for (int ct = 0; ct < 16; ct++) {
        int colb = ct * 8 + q * 2;
        float g0 = sGamma[colb], g1 = sGamma[colb + 1];
        float e0 = sBeta[colb],  e1 = sBeta[colb + 1];
        float y0 = (c[ct][0] - mu0) * inv0 * g0 + e0; y0 = (y0 >= 0.f) ? y0 : aP * y0;
        float y1 = (c[ct][1] - mu0) * inv0 * g1 + e1; y1 = (y1 >= 0.f) ? y1 : aP * y1;
        float y2 = (c[ct][2] - mu1) * inv1 * g0 + e0; y2 = (y2 >= 0.f) ? y2 : aP * y2;
        float y3 = (c[ct][3] - mu1) * inv1 * g1 + e1; y3 = (y3 >= 0.f) ? y3 : aP * y3;
        int ci = ct * 4 + q;
        if (r0 < n) ((__half2*)outh)[(size_t)r0 * 64 + ci] = __floats2half2_rn(y0 * rso0, y1 * rso0);
        if (r1 < n) ((__half2*)outh)[(size_t)r1 * 64 + ci] = __floats2half2_rn(y2 * rso1, y3 * rso1);
    }
}

// ---------------- SCE loss over masked rows ----------------
__global__ void __launch_bounds__(256)
k_loss(const float* __restrict__ recon, const float* __restrict__ x,
       const int* __restrict__ mask_nodes, int m, float* __restrict__ out) {
    __shared__ float part[8];
    int gw   = (blockIdx.x * blockDim.x + threadIdx.x) >> 5;
    int lane = threadIdx.x & 31;
    int wl   = threadIdx.x >> 5;
    float term = 0.f;
    if (gw < m) {
        int node = mask_nodes[gw];
        float4 r = ((const float4*)recon)[(size_t)node * 32 + lane];
        const float* xp = x + (size_t)node * DD + lane * 4;
        float x0 = xp[0], x1 = xp[1], x2 = xp[2], x3 = xp[3];
        float dot = r.x * x0 + r.y * x1 + r.z * x2 + r.w * x3;
        float nr  = r.x * r.x + r.y * r.y + r.z * r.z + r.w * r.w;
        float nx  = x0 * x0 + x1 * x1 + x2 * x2 + x3 * x3;
        #pragma unroll
        for (int o = 16; o; o >>= 1) {
            dot += __shfl_xor_sync(0xffffffffu, dot, o);
            nr  += __shfl_xor_sync(0xffffffffu, nr,  o);
            nx  += __shfl_xor_sync(0xffffffffu, nx,  o);
        }
        if (lane == 0) {
            float cc = dot / (fmaxf(sqrtf(nr), 1e-12f) * fmaxf(sqrtf(nx), 1e-12f));
            float t = 1.f - cc;
            term = t * t;
        }
    }
    if (lane == 0) part[wl] = term;
    __syncthreads();
    if (threadIdx.x == 0) {
        float s = 0.f;
        #pragma unroll
        for (int i = 0; i < 8; i++) s += part[i];
        atomicAdd(out, s / (float)m);
    }
}

// ---------------- launch ----------------
extern "C" void kernel_launch(void* const* d_in, const int* in_sizes, int n_in,
                              void* d_out, int out_size) {
    const float* x     = (const float*)d_in[0];
    const float* token = (const float*)d_in[1];
    const float* W1    = (const float*)d_in[2];
    const float* b1    = (const float*)d_in[3];
    const float* g1    = (const float*)d_in[4];
    const float* be1   = (const float*)d_in[5];
    const float* a1    = (const float*)d_in[6];
    const float* W2    = (const float*)d_in[7];
    const float* b2    = (const float*)d_in[8];
    const float* g2    = (const float*)d_in[9];
    const float* be2   = (const float*)d_in[10];
    const float* a2    = (const float*)d_in[11];
    const float* We2d  = (const float*)d_in[12];
    const float* Wd    = (const float*)d_in[13];
    const float* bd    = (const float*)d_in[14];
    const int*   src   = (const int*)d_in[15];
    const int*   dst   = (const int*)d_in[16];
    const int*   mask  = (const int*)d_in[17];

    const int n = in_sizes[0] / DD;
    const int E = in_sizes[15];
    const int M = in_sizes[17];
    float* out = (float*)d_out;

    float *recon, *tokA, *rs_out, *rs_in;
    __half *S, *agg16, *h2;
    int *deg_out, *deg_in, *maskflag, *rowptr, *fill, *csrc, *bsum;
    cudaGetSymbolAddress((void**)&recon, g_recon);
    cudaGetSymbolAddress((void**)&S,     g_S);
    cudaGetSymbolAddress((void**)&agg16, g_agg16);
    cudaGetSymbolAddress((void**)&h2,    g_h2);
    cudaGetSymbolAddress((void**)&tokA,  g_token);
    cudaGetSymbolAddress((void**)&deg_out, g_deg_out);
    cudaGetSymbolAddress((void**)&deg_in,  g_deg_in);
    cudaGetSymbolAddress((void**)&rs_out, g_rs_out);
    cudaGetSymbolAddress((void**)&rs_in,  g_rs_in);
    cudaGetSymbolAddress((void**)&maskflag, g_maskflag);
    cudaGetSymbolAddress((void**)&rowptr, g_rowptr);
    cudaGetSymbolAddress((void**)&fill,   g_fill);
    cudaGetSymbolAddress((void**)&csrc,   g_csrc);
    cudaGetSymbolAddress((void**)&bsum,   g_bsum);

    const size_t smem = (size_t)(2 * 128 * SROW) * sizeof(__half) + 3 * 128 * sizeof(float);
    cudaFuncSetAttribute(k_gemm, cudaFuncAttributeMaxDynamicSharedMemorySize, (int)smem);

    const int T = 256;
    const int gN = (n + T - 1) / T;
    const int gE = (E + T - 1) / T;
    const int gW = ((n * 32) + T - 1) / T;
    const int gG = (n + 127) / 128;
    const int gL = ((M * 32) + T - 1) / T;
    const int nb = (n + 1 + 1023) / 1024;      // scan tiles covering n+1 entries

    // setup
    k_init <<<gN, T>>>(token, tokA, deg_out, deg_in, fill, maskflag, out, n);
    k_deg  <<<gE, T>>>(src, dst, deg_out, deg_in, E);
    k_post <<<gN, T>>>(mask, maskflag, M, deg_out, deg_in, rs_out, rs_in, n);
    k_scan1<<<nb, 1024>>>(deg_in, rowptr, bsum, n);
    k_scan2<<<1, 128>>>(bsum, nb);
    k_scan3<<<nb, 1024>>>(rowptr, bsum, n);
    k_fill <<<gE, T>>>(src, dst, rowptr, fill, csrc, E);

    // conv1
    k_prep1<<<gW, T>>>(x, tokA, maskflag, rs_out, S, n);
    k_agg  <<<gW, T>>>(S, rowptr, csrc, agg16, n);
    k_gemm <<<gG, 256, smem>>>(agg16, S, nullptr, W1, b1, rs_in, rs_out, g1, be1, a1, maskflag, n, 0, 1);

    // conv2
    k_agg  <<<gW, T>>>(S, rowptr, csrc, agg16, n);
    k_gemm <<<gG, 256, smem>>>(agg16, h2, nullptr, W2, b2, rs_in, rs_out, g2, be2, a2, maskflag, n, 0, 0);

    // enc->dec + re-mask
    k_gemm <<<gG, 256, smem>>>(h2, S, nullptr, We2d, bd, rs_in, rs_out, g2, be2, a2, maskflag, n, 2, 1);

    // decoder conv
    k_agg  <<<gW, T>>>(S, rowptr, csrc, agg16, n);
    k_gemm <<<gG, 256, smem>>>(agg16, nullptr, recon, Wd, bd, rs_in, rs_out, g2, be2, a2, maskflag, n, 1, 0);

    // loss
    k_loss <<<gL, T>>>(recon, x, mask, M, out);
}

// round 10
// speedup vs baseline: 1.3533x; 1.0266x over previous
#include <cuda_runtime.h>
#include <cuda_fp16.h>
#include <cstdint>
#include <stdint.h>
#include <math.h>

#define DD 128
#define NMAX 50000
#define EMAX 800000
#define SROW 136            // smem row stride in halfs (272B, 16B-multiple)

// ---------------- scratch (static device globals) ----------------
__device__ __align__(16) float  g_recon[(size_t)NMAX * DD];   // recon (fp32, loss input)
__device__ __align__(16) __half g_S[(size_t)NMAX * DD];       // rs_out-scaled gather rows
__device__ __align__(16) __half g_agg16[(size_t)NMAX * DD];   // aggregation output (fp16)
__device__ __align__(16) float  g_token[DD];
__device__ int   g_deg_out[NMAX];
__device__ int   g_deg_in[NMAX];
__device__ float g_rs_out[NMAX];
__device__ float g_rs_in[NMAX];
__device__ int   g_maskflag[NMAX];
__device__ int   g_rowptr[NMAX + 1];
__device__ int   g_fill[NMAX];
__device__ int   g_bsum[128];
__device__ int   g_csrc[EMAX];

// ---------------- setup kernels ----------------
__global__ void k_init(const float* __restrict__ token, float* __restrict__ tok,
                       int* __restrict__ deg_out, int* __restrict__ deg_in,
                       int* __restrict__ fill, int* __restrict__ maskflag,
                       float* __restrict__ out, int n) {
    int i = blockIdx.x * blockDim.x + threadIdx.x;
    if (i < n) { deg_out[i] = 0; deg_in[i] = 0; fill[i] = 0; maskflag[i] = 0; }
    if (i < DD) tok[i] = token[i];
    if (i == 0) out[0] = 0.f;
}

__global__ void k_deg(const int* __restrict__ src, const int* __restrict__ dst,
                      int* __restrict__ dout, int* __restrict__ din, int e) {
    int i = blockIdx.x * blockDim.x + threadIdx.x;
    if (i < e) {
        atomicAdd(&dout[src[i]], 1);
        atomicAdd(&din[dst[i]], 1);
    }
}

__global__ void k_post(const int* __restrict__ mask_nodes, int* __restrict__ maskflag, int m,
                       const int* __restrict__ dout, const int* __restrict__ din,
                       float* __restrict__ ro, float* __restrict__ ri, int n) {
    int i = blockIdx.x * blockDim.x + threadIdx.x;
    if (i < n) {
        ro[i] = rsqrtf(fmaxf((float)dout[i], 1.f));
        ri[i] = rsqrtf(fmaxf((float)din[i], 1.f));
    }
    if (i < m) maskflag[mask_nodes[i]] = 1;
}

// ---------------- parallel exclusive scan ----------------
__global__ void __launch_bounds__(1024)
k_scan1(const int* __restrict__ deg, int* __restrict__ rowptr,
        int* __restrict__ bsum, int n) {
    __shared__ int warpsum[32];
    int t = threadIdx.x;
    int gi = blockIdx.x * 1024 + t;
    int v = (gi < n) ? deg[gi] : 0;
    int lane = t & 31, wid = t >> 5;
    int inc = v;
    #pragma unroll
    for (int o = 1; o < 32; o <<= 1) {
        int u = __shfl_up_sync(0xffffffffu, inc, o);
        if (lane >= o) inc += u;
    }
    if (lane == 31) warpsum[wid] = inc;
    __syncthreads();
    if (wid == 0) {
        int w = warpsum[lane];
        #pragma unroll
        for (int o = 1; o < 32; o <<= 1) {
            int u = __shfl_up_sync(0xffffffffu, w, o);
            if (lane >= o) w += u;
        }
        warpsum[lane] = w;
    }
    __syncthreads();
    int woff = (wid > 0) ? warpsum[wid - 1] : 0;
    if (gi <= n) rowptr[gi] = woff + inc - v;
    if (t == 1023) bsum[blockIdx.x] = warpsum[31];
}

__global__ void k_scan2(int* __restrict__ bsum, int nb) {
    __shared__ int sm[128];
    int t = threadIdx.x;
    sm[t] = (t < nb) ? bsum[t] : 0;
    __syncthreads();
    #pragma unroll
    for (int o = 1; o < 128; o <<= 1) {
        int v = (t >= o) ? sm[t - o] : 0;
        __syncthreads();
        sm[t] += v;
        __syncthreads();
    }
    if (t < nb) bsum[t] = (t > 0) ? sm[t - 1] : 0;
}

__global__ void __launch_bounds__(1024)
k_scan3(int* __restrict__ rowptr, const int* __restrict__ bsum, int n) {
    int gi = blockIdx.x * 1024 + threadIdx.x;
    if (gi <= n) rowptr[gi] += bsum[blockIdx.x];
}

__global__ void k_fill(const int* __restrict__ src, const int* __restrict__ dst,
                       const int* __restrict__ rowptr, int* __restrict__ fill,
                       int* __restrict__ csrc, int e) {
    int i = blockIdx.x * blockDim.x + threadIdx.x;
    if (i < e) {
        int d = dst[i];
        int p = rowptr[d] + atomicAdd(&fill[d], 1);
        csrc[p] = src[i];
    }
}

// ---------------- prep: S[v] = (mask? token : x[v]) * rs_out[v] fp16 ----------------
__global__ void __launch_bounds__(256)
k_prep1(const float* __restrict__ x, const float* __restrict__ token,
        const int* __restrict__ maskflag, const float* __restrict__ rs_out,
        __half* __restrict__ S, int n) {
    int w = (blockIdx.x * blockDim.x + threadIdx.x) >> 5;
    int lane = threadIdx.x & 31;
    if (w >= n) return;
    float r = rs_out[w];
    const float* srcp = maskflag[w] ? (token + lane * 4) : (x + (size_t)w * DD + lane * 4);
    __half2 p0 = __floats2half2_rn(srcp[0] * r, srcp[1] * r);
    __half2 p1 = __floats2half2_rn(srcp[2] * r, srcp[3] * r);
    uint2 u;
    *(__half2*)&u.x = p0;
    *(__half2*)&u.y = p1;
    ((uint2*)S)[(size_t)w * 32 + lane] = u;
}

// ---------------- CSR aggregation ----------------
// masked_mode=0: all nodes/edges. masked_mode=1 (decoder): only masked dst,
// skip masked src (their rows are zero by re-mask).
__global__ void __launch_bounds__(256)
k_agg(const __half* __restrict__ S,
      const int* __restrict__ rowptr, const int* __restrict__ csrc,
      const int* __restrict__ maskflag,
      __half* __restrict__ agg, int n, int masked_mode) {
    int w = (blockIdx.x * blockDim.x + threadIdx.x) >> 5;
    int lane = threadIdx.x & 31;
    if (w >= n) return;
    if (masked_mode && !maskflag[w]) return;
    int beg = rowptr[w];
    int end = rowptr[w + 1];
    float4 acc = make_float4(0.f, 0.f, 0.f, 0.f);
    for (int e = beg; e < end; e++) {
        int s = csrc[e];
        if (masked_mode && maskflag[s]) continue;   // zero row, skip gather
        uint2 u = ((const uint2*)S)[(size_t)s * 32 + lane];
        float2 f0 = __half22float2(*(__half2*)&u.x);
        float2 f1 = __half22float2(*(__half2*)&u.y);
        acc.x += f0.x; acc.y += f0.y; acc.z += f1.x; acc.w += f1.y;
    }
    uint2 o;
    *(__half2*)&o.x = __floats2half2_rn(acc.x, acc.y);
    *(__half2*)&o.y = __floats2half2_rn(acc.z, acc.w);
    ((uint2*)agg)[(size_t)w * 32 + lane] = o;
}

// ---------------- mma helper macros (shared by both GEMM kernels) ----------------
#define MMA_LOOP(cacc, aBase, sWu, bRow, bKoff)                                              \
    _Pragma("unroll")                                                                         \
    for (int kb = 0; kb < 8; kb++) {                                                          \
        uint32_t a0, a1, a2, a3;                                                              \
        asm volatile("ldmatrix.sync.aligned.m8n8.x4.shared.b16 {%0,%1,%2,%3}, [%4];"         \
                     : "=r"(a0), "=r"(a1), "=r"(a2), "=r"(a3)                                 \
                     : "r"((aBase) + kb * 32));                                               \
        _Pragma("unroll")                                                                     \
        for (int ng = 0; ng < 8; ng++) {                                                      \
            uint32_t b0, b1, b2, b3;                                                          \
            uint32_t baddr = (sWu) + (uint32_t)((ng * 16 + (bRow)) * (SROW * 2) + kb * 32 + (bKoff)); \
            asm volatile("ldmatrix.sync.aligned.m8n8.x4.shared.b16 {%0,%1,%2,%3}, [%4];"     \
                         : "=r"(b0), "=r"(b1), "=r"(b2), "=r"(b3)                             \
                         : "r"(baddr));                                                       \
            int t0 = ng * 2, t1 = ng * 2 + 1;                                                 \
            asm volatile("mma.sync.aligned.m16n8k16.row.col.f32.f16.f16.f32 "                \
                         "{%0,%1,%2,%3}, {%4,%5,%6,%7}, {%8,%9}, {%0,%1,%2,%3};"             \
                         : "+f"(cacc[t0][0]), "+f"(cacc[t0][1]), "+f"(cacc[t0][2]), "+f"(cacc[t0][3]) \
                         : "r"(a0), "r"(a1), "r"(a2), "r"(a3), "r"(b0), "r"(b1));             \
            asm volatile("mma.sync.aligned.m16n8k16.row.col.f32.f16.f16.f32 "                \
                         "{%0,%1,%2,%3}, {%4,%5,%6,%7}, {%8,%9}, {%0,%1,%2,%3};"             \
                         : "+f"(cacc[t1][0]), "+f"(cacc[t1][1]), "+f"(cacc[t1][2]), "+f"(cacc[t1][3]) \
                         : "r"(a0), "r"(a1), "r"(a2), "r"(a3), "r"(b2), "r"(b3));             \
        }                                                                                     \
    }

#define STAGE_W(Wp, sW)                                                                       \
    _Pragma("unroll")                                                                         \
    for (int it = 0; it < 32; it++) {                                                         \
        int idx = it * 256 + threadIdx.x;                                                     \
        int base2 = idx * 2;                                                                  \
        int cc = base2 >> 7, kk = base2 & 127;                                                \
        float w0 = (Wp)[base2], w1 = (Wp)[base2 + 1];                                         \
        *(__half2*)&(sW)[cc * SROW + kk] = __floats2half2_rn(w0, w1);                         \
    }

// ---------------- tensor-core GEMM (single): conv1 (mode0) / decoder (mode1) ----------------
// mode 0: (acc+b)*rs_in -> LN -> PReLU -> fp16 *rs_out -> outh
// mode 1: (acc+b)*rs_in -> fp32 -> outf
__global__ void __launch_bounds__(256, 2)
k_gemm(const __half* __restrict__ in, __half* __restrict__ outh, float* __restrict__ outf,
       const float* __restrict__ W, const float* __restrict__ bias,
       const float* __restrict__ rs_in, const float* __restrict__ rs_out,
       const float* __restrict__ gamma, const float* __restrict__ beta,
       const float* __restrict__ alpha,
       int n, int mode) {
    extern __shared__ char smraw[];
    __half* sA = (__half*)smraw;
    __half* sW = sA + 128 * SROW;
    float* sBias  = (float*)(sW + 128 * SROW);
    float* sGamma = sBias + 128;
    float* sBeta  = sGamma + 128;

    const int tid  = threadIdx.x;
    const int row0 = blockIdx.x * 128;

    #pragma unroll
    for (int it = 0; it < 8; it++) {
        int idx = it * 256 + tid;
        int r = idx >> 4, c8 = idx & 15;
        uint4 v = make_uint4(0u, 0u, 0u, 0u);
        int gr = row0 + r;
        if (gr < n) v = ((const uint4*)in)[(size_t)gr * 16 + c8];
        *(uint4*)&sA[r * SROW + c8 * 8] = v;
    }
    STAGE_W(W, sW);
    if (tid < 128) {
        sBias[tid]  = bias[tid];
        sGamma[tid] = (mode == 0) ? gamma[tid] : 0.f;
        sBeta[tid]  = (mode == 0) ? beta[tid] : 0.f;
    }
    __syncthreads();

    const int warp = tid >> 5;
    const int lane = tid & 31;

    float c[16][4];
    #pragma unroll
    for (int i = 0; i < 16; i++) { c[i][0]=0.f; c[i][1]=0.f; c[i][2]=0.f; c[i][3]=0.f; }

    uint32_t sAu = (uint32_t)__cvta_generic_to_shared(sA);
    uint32_t sWu = (uint32_t)__cvta_generic_to_shared(sW);
    uint32_t aBase = sAu + (uint32_t)((warp * 16 + (lane & 15)) * (SROW * 2) + (lane >> 4) * 16);
    uint32_t bRow  = (uint32_t)((lane >> 4) * 8 + (lane & 7));
    uint32_t bKoff = (uint32_t)(((lane >> 3) & 1) * 16);

    MMA_LOOP(c, aBase, sWu, bRow, bKoff);

    int r0 = row0 + warp * 16 + (lane >> 2);
    int r1 = r0 + 8;
    int q  = lane & 3;

    float rsi0 = (r0 < n) ? rs_in[r0] : 1.f;
    float rsi1 = (r1 < n) ? rs_in[r1] : 1.f;
    #pragma unroll
    for (int ct = 0; ct < 16; ct++) {
        int colb = ct * 8 + q * 2;
        float bb0 = sBias[colb], bb1 = sBias[colb + 1];
        c[ct][0] = (c[ct][0] + bb0) * rsi0;
        c[ct][1] = (c[ct][1] + bb1) * rsi0;
        c[ct][2] = (c[ct][2] + bb0) * rsi1;
        c[ct][3] = (c[ct][3] + bb1) * rsi1;
    }

    if (mode == 1) {
        #pragma unroll
        for (int ct = 0; ct < 16; ct++) {
            int ci = ct * 4 + q;
            if (r0 < n) ((float2*)outf)[(size_t)r0 * 64 + ci] = make_float2(c[ct][0], c[ct][1]);
            if (r1 < n) ((float2*)outf)[(size_t)r1 * 64 + ci] = make_float2(c[ct][2], c[ct][3]);
        }
        return;
    }

    float s0 = 0.f, ss0 = 0.f, s1 = 0.f, ss1 = 0.f;
    #pragma unroll
    for (int ct = 0; ct < 16; ct++) {
        s0  += c[ct][0] + c[ct][1];
        ss0 += c[ct][0] * c[ct][0] + c[ct][1] * c[ct][1];
        s1  += c[ct][2] + c[ct][3];
        ss1 += c[ct][2] * c[ct][2] + c[ct][3] * c[ct][3];
    }
    #pragma unroll
    for (int o = 1; o <= 2; o <<= 1) {
        s0  += __shfl_xor_sync(0xffffffffu, s0,  o);
        ss0 += __shfl_xor_sync(0xffffffffu, ss0, o);
        s1  += __shfl_xor_sync(0xffffffffu, s1,  o);
        ss1 += __shfl_xor_sync(0xffffffffu, ss1, o);
    }
    float mu0 = s0 * (1.f / 128.f);
    float mu1 = s1 * (1.f / 128.f);
    float inv0 = rsqrtf(ss0 * (1.f / 128.f) - mu0 * mu0 + 1e-5f);
    float inv1 = rsqrtf(ss1 * (1.f / 128.f) - mu1 * mu1 + 1e-5f);
    float aP = alpha[0];
    float rso0 = (r0 < n) ? rs_out[r0] : 1.f;
    float rso1 = (r1 < n) ? rs_out[r1] : 1.f;
    #pragma unroll
    for (int ct = 0; ct < 16; ct++) {
        int colb = ct * 8 + q * 2;
        float g0 = sGamma[colb], g1 = sGamma[colb + 1];
        float e0 = sBeta[colb],  e1 = sBeta[colb + 1];
        float y0 = (c[ct][0] - mu0) * inv0 * g0 + e0; y0 = (y0 >= 0.f) ? y0 : aP * y0;
        float y1 = (c[ct][1] - mu0) * inv0 * g1 + e1; y1 = (y1 >= 0.f) ? y1 : aP * y1;
        float y2 = (c[ct][2] - mu1) * inv1 * g0 + e0; y2 = (y2 >= 0.f) ? y2 : aP * y2;
        float y3 = (c[ct][3] - mu1) * inv1 * g1 + e1; y3 = (y3 >= 0.f) ? y3 : aP * y3;
        int ci = ct * 4 + q;
        if (r0 < n) ((__half2*)outh)[(size_t)r0 * 64 + ci] = __floats2half2_rn(y0 * rso0, y1 * rso0);
        if (r1 < n) ((__half2*)outh)[(size_t)r1 * 64 + ci] = __floats2half2_rn(y2 * rso1, y3 * rso1);
    }
}

// ---------------- fused conv2-GEMM (LN+PReLU) + enc->dec-GEMM (re-mask, *rs_out) ----------------
// h2 never leaves smem: first GEMM writes y back into sA (warp-local rows),
// then sW is restaged with We2d and the second GEMM runs on it.
__global__ void __launch_bounds__(256, 2)
k_gemm_fused(const __half* __restrict__ in, __half* __restrict__ outS,
             const float* __restrict__ W2, const float* __restrict__ bias2,
             const float* __restrict__ We2d,
             const float* __restrict__ rs_in, const float* __restrict__ rs_out,
             const float* __restrict__ gamma, const float* __restrict__ beta,
             const float* __restrict__ alpha,
             const int* __restrict__ maskflag, int n) {
    extern __shared__ char smraw[];
    __half* sA = (__half*)smraw;
    __half* sW = sA + 128 * SROW;
    float* sBias  = (float*)(sW + 128 * SROW);
    float* sGamma = sBias + 128;
    float* sBeta  = sGamma + 128;

    const int tid  = threadIdx.x;
    const int row0 = blockIdx.x * 128;

    #pragma unroll
    for (int it = 0; it < 8; it++) {
        int idx = it * 256 + tid;
        int r = idx >> 4, c8 = idx & 15;
        uint4 v = make_uint4(0u, 0u, 0u, 0u);
        int gr = row0 + r;
        if (gr < n) v = ((const uint4*)in)[(size_t)gr * 16 + c8];
        *(uint4*)&sA[r * SROW + c8 * 8] = v;
    }
    STAGE_W(W2, sW);
    if (tid < 128) {
        sBias[tid]  = bias2[tid];
        sGamma[tid] = gamma[tid];
        sBeta[tid]  = beta[tid];
    }
    __syncthreads();

    const int warp = tid >> 5;
    const int lane = tid & 31;

    float c[16][4];
    #pragma unroll
    for (int i = 0; i < 16; i++) { c[i][0]=0.f; c[i][1]=0.f; c[i][2]=0.f; c[i][3]=0.f; }

    uint32_t sAu = (uint32_t)__cvta_generic_to_shared(sA);
    uint32_t sWu = (uint32_t)__cvta_generic_to_shared(sW);
    uint32_t aBase = sAu + (uint32_t)((warp * 16 + (lane & 15)) * (SROW * 2) + (lane >> 4) * 16);
    uint32_t bRow  = (uint32_t)((lane >> 4) * 8 + (lane & 7));
    uint32_t bKoff = (uint32_t)(((lane >> 3) & 1) * 16);

    MMA_LOOP(c, aBase, sWu, bRow, bKoff);

    // ---- epilogue 1: bias + rs_in, LN (quad), PReLU -> write fp16 into sA (warp-local rows)
    int lr0 = warp * 16 + (lane >> 2);          // local row in tile
    int lr1 = lr0 + 8;
    int r0 = row0 + lr0;
    int r1 = row0 + lr1;
    int q  = lane & 3;

    float rsi0 = (r0 < n) ? rs_in[r0] : 1.f;
    float rsi1 = (r1 < n) ? rs_in[r1] : 1.f;
    float s0 = 0.f, ss0 = 0.f, s1 = 0.f, ss1 = 0.f;
    #pragma unroll
    for (int ct = 0; ct < 16; ct++) {
        int colb = ct * 8 + q * 2;
        float bb0 = sBias[colb], bb1 = sBias[colb + 1];
        c[ct][0] = (c[ct][0] + bb0) * rsi0;
        c[ct][1] = (c[ct][1] + bb1) * rsi0;
        c[ct][2] = (c[ct][2] + bb0) * rsi1;
        c[ct][3] = (c[ct][3] + bb1) * rsi1;
        s0  += c[ct][0] + c[ct][1];
        ss0 += c[ct][0] * c[ct][0] + c[ct][1] * c[ct][1];
        s1  += c[ct][2] + c[ct][3];
        ss1 += c[ct][2] * c[ct][2] + c[ct][3] * c[ct][3];
    }
    #pragma unroll
    for (int o = 1; o <= 2; o <<= 1) {
        s0  += __shfl_xor_sync(0xffffffffu, s0,  o);
        ss0 += __shfl_xor_sync(0xffffffffu, ss0, o);
        s1  += __shfl_xor_sync(0xffffffffu, s1,  o);
        ss1 += __shfl_xor_sync(0xffffffffu, ss1, o);
    }
    float mu0 = s0 * (1.f / 128.f);
    float mu1 = s1 * (1.f / 128.f);
    float inv0 = rsqrtf(ss0 * (1.f / 128.f) - mu0 * mu0 + 1e-5f);
    float inv1 = rsqrtf(ss1 * (1.f / 128.f) - mu1 * mu1 + 1e-5f);
    float aP = alpha[0];
    #pragma unroll
    for (int ct = 0; ct < 16; ct++) {
        int colb = ct * 8 + q * 2;
        float g0 = sGamma[colb], g1 = sGamma[colb + 1];
        float e0 = sBeta[colb],  e1 = sBeta[colb + 1];
        float y0 = (c[ct][0] - mu0) * inv0 * g0 + e0; y0 = (y0 >= 0.f) ? y0 : aP * y0;
        float y1 = (c[ct][1] - mu0) * inv0 * g1 + e1; y1 = (y1 >= 0.f) ? y1 : aP * y1;
        float y2 = (c[ct][2] - mu1) * inv1 * g0 + e0; y2 = (y2 >= 0.f) ? y2 : aP * y2;
        float y3 = (c[ct][3] - mu1) * inv1 * g1 + e1; y3 = (y3 >= 0.f) ? y3 : aP * y3;
        *(__half2*)&sA[lr0 * SROW + colb] = __floats2half2_rn(y0, y1);
        *(__half2*)&sA[lr1 * SROW + colb] = __floats2half2_rn(y2, y3);
    }

    // ---- restage sW with We2d; sA rewritten warp-locally (safe) ----
    __syncthreads();
    STAGE_W(We2d, sW);
    __syncthreads();

    #pragma unroll
    for (int i = 0; i < 16; i++) { c[i][0]=0.f; c[i][1]=0.f; c[i][2]=0.f; c[i][3]=0.f; }
    MMA_LOOP(c, aBase, sWu, bRow, bKoff);

    // ---- epilogue 2: re-mask + *rs_out -> outS (fp16) ----
    float rso0 = (r0 < n) ? ((maskflag[r0]) ? 0.f : rs_out[r0]) : 0.f;
    float rso1 = (r1 < n) ? ((maskflag[r1]) ? 0.f : rs_out[r1]) : 0.f;
    #pragma unroll
    for (int ct = 0; ct < 16; ct++) {
        int ci = ct * 4 + q;
        if (r0 < n) ((__half2*)outS)[(size_t)r0 * 64 + ci] = __floats2half2_rn(c[ct][0] * rso0, c[ct][1] * rso0);
        if (r1 < n) ((__half2*)outS)[(size_t)r1 * 64 + ci] = __floats2half2_rn(c[ct][2] * rso1, c[ct][3] * rso1);
    }
}

// ---------------- SCE loss over masked rows ----------------
__global__ void __launch_bounds__(256)
k_loss(const float* __restrict__ recon, const float* __restrict__ x,
       const int* __restrict__ mask_nodes, int m, float* __restrict__ out) {
    __shared__ float part[8];
    int gw   = (blockIdx.x * blockDim.x + threadIdx.x) >> 5;
    int lane = threadIdx.x & 31;
    int wl   = threadIdx.x >> 5;
    float term = 0.f;
    if (gw < m) {
        int node = mask_nodes[gw];
        float4 r = ((const float4*)recon)[(size_t)node * 32 + lane];
        const float* xp = x + (size_t)node * DD + lane * 4;
        float x0 = xp[0], x1 = xp[1], x2 = xp[2], x3 = xp[3];
        float dot = r.x * x0 + r.y * x1 + r.z * x2 + r.w * x3;
        float nr  = r.x * r.x + r.y * r.y + r.z * r.z + r.w * r.w;
        float nx  = x0 * x0 + x1 * x1 + x2 * x2 + x3 * x3;
        #pragma unroll
        for (int o = 16; o; o >>= 1) {
            dot += __shfl_xor_sync(0xffffffffu, dot, o);
            nr  += __shfl_xor_sync(0xffffffffu, nr,  o);
            nx  += __shfl_xor_sync(0xffffffffu, nx,  o);
        }
        if (lane == 0) {
            float cc = dot / (fmaxf(sqrtf(nr), 1e-12f) * fmaxf(sqrtf(nx), 1e-12f));
            float t = 1.f - cc;
            term = t * t;
        }
    }
    if (lane == 0) part[wl] = term;
    __syncthreads();
    if (threadIdx.x == 0) {
        float s = 0.f;
        #pragma unroll
        for (int i = 0; i < 8; i++) s += part[i];
        atomicAdd(out, s / (float)m);
    }
}

// ---------------- launch ----------------
extern "C" void kernel_launch(void* const* d_in, const int* in_sizes, int n_in,
                              void* d_out, int out_size) {
    const float* x     = (const float*)d_in[0];
    const float* token = (const float*)d_in[1];
    const float* W1    = (const float*)d_in[2];
    const float* b1    = (const float*)d_in[3];
    const float* g1    = (const float*)d_in[4];
    const float* be1   = (const float*)d_in[5];
    const float* a1    = (const float*)d_in[6];
    const float* W2    = (const float*)d_in[7];
    const float* b2    = (const float*)d_in[8];
    const float* g2    = (const float*)d_in[9];
    const float* be2   = (const float*)d_in[10];
    const float* a2    = (const float*)d_in[11];
    const float* We2d  = (const float*)d_in[12];
    const float* Wd    = (const float*)d_in[13];
    const float* bd    = (const float*)d_in[14];
    const int*   src   = (const int*)d_in[15];
    const int*   dst   = (const int*)d_in[16];
    const int*   mask  = (const int*)d_in[17];

    const int n = in_sizes[0] / DD;
    const int E = in_sizes[15];
    const int M = in_sizes[17];
    float* out = (float*)d_out;

    float *recon, *tokA, *rs_out, *rs_in;
    __half *S, *agg16;
    int *deg_out, *deg_in, *maskflag, *rowptr, *fill, *csrc, *bsum;
    cudaGetSymbolAddress((void**)&recon, g_recon);
    cudaGetSymbolAddress((void**)&S,     g_S);
    cudaGetSymbolAddress((void**)&agg16, g_agg16);
    cudaGetSymbolAddress((void**)&tokA,  g_token);
    cudaGetSymbolAddress((void**)&deg_out, g_deg_out);
    cudaGetSymbolAddress((void**)&deg_in,  g_deg_in);
    cudaGetSymbolAddress((void**)&rs_out, g_rs_out);
    cudaGetSymbolAddress((void**)&rs_in,  g_rs_in);
    cudaGetSymbolAddress((void**)&maskflag, g_maskflag);
    cudaGetSymbolAddress((void**)&rowptr, g_rowptr);
    cudaGetSymbolAddress((void**)&fill,   g_fill);
    cudaGetSymbolAddress((void**)&csrc,   g_csrc);
    cudaGetSymbolAddress((void**)&bsum,   g_bsum);

    const size_t smem = (size_t)(2 * 128 * SROW) * sizeof(__half) + 3 * 128 * sizeof(float);
    cudaFuncSetAttribute(k_gemm, cudaFuncAttributeMaxDynamicSharedMemorySize, (int)smem);
    cudaFuncSetAttribute(k_gemm_fused, cudaFuncAttributeMaxDynamicSharedMemorySize, (int)smem);

    const int T = 256;
    const int gN = (n + T - 1) / T;
    const int gE = (E + T - 1) / T;
    const int gW = ((n * 32) + T - 1) / T;
    const int gG = (n + 127) / 128;
    const int gL = ((M * 32) + T - 1) / T;
    const int nb = (n + 1 + 1023) / 1024;

    // setup
    k_init <<<gN, T>>>(token, tokA, deg_out, deg_in, fill, maskflag, out, n);
    k_deg  <<<gE, T>>>(src, dst, deg_out, deg_in, E);
    k_post <<<gN, T>>>(mask, maskflag, M, deg_out, deg_in, rs_out, rs_in, n);
    k_scan1<<<nb, 1024>>>(deg_in, rowptr, bsum, n);
    k_scan2<<<1, 128>>>(bsum, nb);
    k_scan3<<<nb, 1024>>>(rowptr, bsum, n);
    k_fill <<<gE, T>>>(src, dst, rowptr, fill, csrc, E);

    // conv1: prep -> agg -> GEMM(LN+PReLU, *rs_out) -> S
    k_prep1<<<gW, T>>>(x, tokA, maskflag, rs_out, S, n);
    k_agg  <<<gW, T>>>(S, rowptr, csrc, maskflag, agg16, n, 0);
    k_gemm <<<gG, 256, smem>>>(agg16, S, nullptr, W1, b1, rs_in, rs_out, g1, be1, a1, n, 0);

    // conv2 + enc->dec (fused): agg -> [GEMM+LN+PReLU ; GEMM+re-mask+*rs_out] -> S
    k_agg  <<<gW, T>>>(S, rowptr, csrc, maskflag, agg16, n, 0);
    k_gemm_fused<<<gG, 256, smem>>>(agg16, S, W2, b2, We2d, rs_in, rs_out, g2, be2, a2, maskflag, n);

    // decoder conv (masked dst only, skip masked src): agg -> GEMM -> recon (fp32)
    k_agg  <<<gW, T>>>(S, rowptr, csrc, maskflag, agg16, n, 1);
    k_gemm <<<gG, 256, smem>>>(agg16, nullptr, recon, Wd, bd, rs_in, rs_out, g2, be2, a2, n, 1);

    // loss
    k_loss <<<gL, T>>>(recon, x, mask, M, out);
}